// round 14
// baseline (speedup 1.0000x reference)
#include <cuda_runtime.h>
#include <cuda_fp16.h>
#include <cstdint>

#define NN 100000
#define NE 1600000

// ---------------- scratch (static __device__ — allocation-free) ----------------
__device__ int    g_deg[NN];
__device__ int    g_cursor[NN];
__device__ int    g_rowptr[NN + 1];
__device__ int    g_bsum[256];
__device__ int    g_bsrc[NE];
__device__ float4 g_battr[NE];
__device__ float  g_xd[NN * 64];
__device__ __half g_xs_h[NN * 64];      // fp16 (tf32-equivalent mantissa)
__device__ float  g_cat0[NN * 96];      // layer0 concat input [x | s mean mx mn std]
__device__ __half g_big_h[NN * 384];    // layer1 concat input, fp16
__device__ float  g_h1[NN * 64];
__device__ float  g_h2[NN * 64];
__device__ float  g_hn[NN * 16];
// folded weights
__device__ float  g_Wc0[4 * 16],  g_xb0[16];
__device__ float  g_Wc1[4 * 64],  g_xb1[64];
__device__ float  g_Wcomb0[96 * 64],  g_bcomb0[64];
__device__ float  g_Wcomb1[384 * 64], g_bcomb1[64];

// ---------------- CSR build ----------------
__global__ void k_count(const int* __restrict__ dst) {
    int e = blockIdx.x * blockDim.x + threadIdx.x;
    if (e < NE) atomicAdd(&g_deg[dst[e]], 1);
}

__global__ void k_scan1() {
    __shared__ int s[1024];
    int i = blockIdx.x * 1024 + threadIdx.x;
    int v = (i < NN) ? g_deg[i] : 0;
    s[threadIdx.x] = v;
    __syncthreads();
    for (int off = 1; off < 1024; off <<= 1) {
        int t = (threadIdx.x >= off) ? s[threadIdx.x - off] : 0;
        __syncthreads();
        s[threadIdx.x] += t;
        __syncthreads();
    }
    if (i < NN) g_rowptr[i] = s[threadIdx.x] - v;   // exclusive within block
    if (threadIdx.x == 1023) g_bsum[blockIdx.x] = s[1023];
}

// merged scan2+scan3: each block computes its own bsum prefix with one warp.
// Also initializes cursor = rowptr so scatter needs only ONE random access.
__global__ void k_scan23() {
    __shared__ int base;
    int b = blockIdx.x, tid = threadIdx.x;
    if (tid < 32) {
        int sum = 0;
        for (int i = tid; i < b; i += 32) sum += g_bsum[i];
        #pragma unroll
        for (int off = 16; off > 0; off >>= 1)
            sum += __shfl_xor_sync(0xffffffffu, sum, off);
        if (tid == 0) base = sum;
    }
    __syncthreads();
    int i = b * 1024 + tid;
    if (i < NN) {
        int rp = g_rowptr[i] + base;
        g_rowptr[i] = rp;
        g_cursor[i] = rp;
    }
    if (i == 0) g_rowptr[NN] = NE;
}

__global__ void k_scatter(const int* __restrict__ src, const int* __restrict__ dst,
                          const float* __restrict__ ea) {
    int e = blockIdx.x * blockDim.x + threadIdx.x;
    if (e >= NE) return;
    int d = dst[e];
    int p = atomicAdd(&g_cursor[d], 1);          // cursor pre-seeded with rowptr
    g_bsrc[p]  = src[e];
    g_battr[p] = ((const float4*)ea)[e];
}

// ---------------- fused weight folding + layer-0 xd/xs precompute ----------------
// blocks [0,121): folds (edge0 | edge1 | post0 | post1)
// blocks [121,...): xd0/xs0 + copy x into cat0 (self-contained bias fold)
#define FOLD_BLOCKS 121
__global__ void k_fold_xdxs(
    const float* __restrict__ We0,  const float* __restrict__ be0,
    const float* __restrict__ Wpre0,const float* __restrict__ bpre0,
    const float* __restrict__ We1,  const float* __restrict__ be1,
    const float* __restrict__ Wpre1,const float* __restrict__ bpre1,
    const float* __restrict__ Wpost0,const float* __restrict__ bpost0,
    const float* __restrict__ Wlin0, const float* __restrict__ blin0,
    const float* __restrict__ Wpost1,const float* __restrict__ bpost1,
    const float* __restrict__ Wlin1, const float* __restrict__ blin1,
    const float* __restrict__ x)
{
    if (blockIdx.x < FOLD_BLOCKS) {
        int idx = blockIdx.x * blockDim.x + threadIdx.x;
        if (idx < 16) {
            int f = idx;
            float a0 = 0, a1 = 0, a2 = 0, a3 = 0, b = bpre0[f];
            for (int j = 0; j < 16; j++) {
                float wv = Wpre0[(32 + j) * 16 + f];
                a0 = fmaf(We0[0 * 16 + j], wv, a0);
                a1 = fmaf(We0[1 * 16 + j], wv, a1);
                a2 = fmaf(We0[2 * 16 + j], wv, a2);
                a3 = fmaf(We0[3 * 16 + j], wv, a3);
                b  = fmaf(be0[j], wv, b);
            }
            g_Wc0[f] = a0; g_Wc0[16 + f] = a1; g_Wc0[32 + f] = a2; g_Wc0[48 + f] = a3;
            g_xb0[f] = b;
        } else if (idx < 80) {
            int f = idx - 16;
            float a0 = 0, a1 = 0, a2 = 0, a3 = 0, b = bpre1[f];
            for (int j = 0; j < 64; j++) {
                float wv = Wpre1[(128 + j) * 64 + f];
                a0 = fmaf(We1[0 * 64 + j], wv, a0);
                a1 = fmaf(We1[1 * 64 + j], wv, a1);
                a2 = fmaf(We1[2 * 64 + j], wv, a2);
                a3 = fmaf(We1[3 * 64 + j], wv, a3);
                b  = fmaf(be1[j], wv, b);
            }
            g_Wc1[f] = a0; g_Wc1[64 + f] = a1; g_Wc1[128 + f] = a2; g_Wc1[192 + f] = a3;
            g_xb1[f] = b;
        } else if (idx < 80 + 96 * 64 + 64) {
            int t = idx - 80;
            if (t < 96 * 64) {
                int k = t >> 6, f = t & 63;
                float a = 0;
                for (int j = 0; j < 64; j++) a = fmaf(Wpost0[k * 64 + j], Wlin0[j * 64 + f], a);
                g_Wcomb0[t] = a;
            } else {
                int f = t - 96 * 64;
                float a = blin0[f];
                for (int j = 0; j < 64; j++) a = fmaf(bpost0[j], Wlin0[j * 64 + f], a);
                g_bcomb0[f] = a;
            }
        } else if (idx < 80 + 96 * 64 + 64 + 384 * 64 + 64) {
            int t = idx - (80 + 96 * 64 + 64);
            if (t < 384 * 64) {
                int k = t >> 6, f = t & 63;
                float a = 0;
                for (int j = 0; j < 64; j++) a = fmaf(Wpost1[k * 64 + j], Wlin1[j * 64 + f], a);
                g_Wcomb1[t] = a;
            } else {
                int f = t - 384 * 64;
                float a = blin1[f];
                for (int j = 0; j < 64; j++) a = fmaf(bpost1[j], Wlin1[j * 64 + f], a);
                g_bcomb1[f] = a;
            }
        }
    } else {
        int t = (blockIdx.x - FOLD_BLOCKS) * blockDim.x + threadIdx.x;
        if (t >= NN * 32) return;
        int v = t >> 5, l = t & 31, f = l & 15;
        int rbase = (l < 16) ? 0 : 16;
        float acc = 0.f;
        if (l < 16) {                      // inline xb0 fold (independent of fold blocks)
            acc = bpre0[f];
            #pragma unroll
            for (int j = 0; j < 16; j++)
                acc = fmaf(be0[j], Wpre0[(32 + j) * 16 + f], acc);
        }
        const float* xr = x + v * 16;
        #pragma unroll
        for (int j = 0; j < 16; j++)
            acc = fmaf(xr[j], Wpre0[(rbase + j) * 16 + f], acc);
        if (l < 16) { g_xd[v * 16 + f] = acc; g_cat0[v * 96 + f] = xr[f]; }
        else        { g_xs_h[v * 16 + f] = __float2half(acc); }
    }
}

// ---------------- PNA aggregation layer 0 (F=16, 16 lanes/node; serial loop) ----------------
__global__ __launch_bounds__(256) void k_agg0() {
    int tid = threadIdx.x;
    int v = blockIdx.x * 16 + (tid >> 4);
    int f = tid & 15;
    if (v >= NN) return;
    int rs = g_rowptr[v], re = g_rowptr[v + 1];
    float xdv = g_xd[v * 16 + f];
    float w0 = g_Wc0[f], w1 = g_Wc0[16 + f], w2 = g_Wc0[32 + f], w3 = g_Wc0[48 + f];
    float s = 0, sq = 0, mx = -3.402823e38f, mn = 3.402823e38f;
    #pragma unroll 2
    for (int e = rs; e < re; e++) {
        int sid = g_bsrc[e];
        float4 a = g_battr[e];
        float m = xdv + __half2float(g_xs_h[sid * 16 + f]);
        m = fmaf(a.x, w0, fmaf(a.y, w1, fmaf(a.z, w2, fmaf(a.w, w3, m))));
        s += m; sq = fmaf(m, m, sq); mx = fmaxf(mx, m); mn = fminf(mn, m);
    }
    int cnt = re - rs;
    float den = (float)(cnt > 0 ? cnt : 1);
    float mean = s / den, msq = sq / den;
    float sd = sqrtf(fmaxf(msq - mean * mean, 0.f) + 1e-5f);
    if (cnt == 0) { mx = 0.f; mn = 0.f; }
    float* o = g_cat0 + v * 96 + 16 + f;
    o[0] = s; o[16] = mean; o[32] = mx; o[48] = mn; o[64] = sd;
}

// ---------------- PNA aggregation layer 1 (F=64, 64 lanes/node; serial loop) ----------------
__global__ __launch_bounds__(256) void k_agg1() {
    int tid = threadIdx.x;
    int v = blockIdx.x * 4 + (tid >> 6);
    int f = tid & 63;
    if (v >= NN) return;
    int rs = g_rowptr[v], re = g_rowptr[v + 1];
    float xdv = g_xd[v * 64 + f];
    float w0 = g_Wc1[f], w1 = g_Wc1[64 + f], w2 = g_Wc1[128 + f], w3 = g_Wc1[192 + f];
    float s = 0, sq = 0, mx = -3.402823e38f, mn = 3.402823e38f;
    #pragma unroll 2
    for (int e = rs; e < re; e++) {
        int sid = g_bsrc[e];
        float4 a = g_battr[e];
        float m = xdv + __half2float(g_xs_h[sid * 64 + f]);
        m = fmaf(a.x, w0, fmaf(a.y, w1, fmaf(a.z, w2, fmaf(a.w, w3, m))));
        s += m; sq = fmaf(m, m, sq); mx = fmaxf(mx, m); mn = fminf(mn, m);
    }
    int cnt = re - rs;
    float den = (float)(cnt > 0 ? cnt : 1);
    float mean = s / den, msq = sq / den;
    float sd = sqrtf(fmaxf(msq - mean * mean, 0.f) + 1e-5f);
    if (cnt == 0) { mx = 0.f; mn = 0.f; }
    __half* o = g_big_h + v * 384 + 64 + f;
    o[0]   = __float2half(s);
    o[64]  = __float2half(mean);
    o[128] = __float2half(mx);
    o[192] = __float2half(mn);
    o[256] = __float2half(sd);
}

// ================ tf32 tensor-core GEMM: C[M,64] = A[M,KC*32] @ W + bias ================
// HA: A is __half; HC/HC2: outputs stored as __half
#define TA 36
#define TB 72

__device__ __forceinline__ uint32_t f2tf32(float v) {
    uint32_t t;
    asm("cvt.rna.tf32.f32 %0, %1;" : "=r"(t) : "f"(v));
    return t;
}

template<int KC, bool RELU, bool HA, bool HC, bool HC2>
__global__ __launch_bounds__(128) void k_gemm_tf32(
    const void* __restrict__ Av, int lda,
    const float* __restrict__ W,       // [KC*32, 64] fp32 (global)
    const float* __restrict__ bias,    // [64] or nullptr
    void* __restrict__ Cv, int ldc,
    void* __restrict__ C2v, int ldc2)  // optional second store (nullptr to skip)
{
    __shared__ float sA[128 * TA];
    __shared__ float sB[32 * TB];
    int tid = threadIdx.x;
    int lane = tid & 31, w = tid >> 5;
    int rowBase = blockIdx.x * 128;

    float acc[2][8][4];
    #pragma unroll
    for (int mf = 0; mf < 2; mf++)
        #pragma unroll
        for (int j = 0; j < 8; j++)
            #pragma unroll
            for (int q = 0; q < 4; q++) acc[mf][j][q] = 0.f;

    for (int kc = 0; kc < KC; kc++) {
        #pragma unroll
        for (int i = 0; i < 32; i++) {
            int idx = tid + i * 128;
            int r = idx >> 5, k = idx & 31;
            int v = rowBase + r;
            float val = 0.f;
            if (v < NN) {
                if (HA) val = __half2float(((const __half*)Av)[v * lda + kc * 32 + k]);
                else    val = ((const float*)Av)[v * lda + kc * 32 + k];
            }
            sA[r * TA + k] = __uint_as_float(f2tf32(val));
        }
        #pragma unroll
        for (int i = 0; i < 16; i++) {
            int idx = tid + i * 128;
            int k = idx >> 6, n = idx & 63;
            sB[k * TB + n] = __uint_as_float(f2tf32(W[(kc * 32 + k) * 64 + n]));
        }
        __syncthreads();
        #pragma unroll
        for (int ks = 0; ks < 4; ks++) {
            int kk = ks * 8;
            uint32_t a[2][4];
            #pragma unroll
            for (int mf = 0; mf < 2; mf++) {
                int r = w * 32 + mf * 16 + (lane >> 2);
                a[mf][0] = __float_as_uint(sA[r * TA + kk + (lane & 3)]);
                a[mf][1] = __float_as_uint(sA[(r + 8) * TA + kk + (lane & 3)]);
                a[mf][2] = __float_as_uint(sA[r * TA + kk + (lane & 3) + 4]);
                a[mf][3] = __float_as_uint(sA[(r + 8) * TA + kk + (lane & 3) + 4]);
            }
            #pragma unroll
            for (int j = 0; j < 8; j++) {
                uint32_t b0 = __float_as_uint(sB[(kk + (lane & 3)) * TB + j * 8 + (lane >> 2)]);
                uint32_t b1 = __float_as_uint(sB[(kk + (lane & 3) + 4) * TB + j * 8 + (lane >> 2)]);
                #pragma unroll
                for (int mf = 0; mf < 2; mf++) {
                    asm volatile(
                        "mma.sync.aligned.m16n8k8.row.col.f32.tf32.tf32.f32 "
                        "{%0,%1,%2,%3}, {%4,%5,%6,%7}, {%8,%9}, {%0,%1,%2,%3};"
                        : "+f"(acc[mf][j][0]), "+f"(acc[mf][j][1]),
                          "+f"(acc[mf][j][2]), "+f"(acc[mf][j][3])
                        : "r"(a[mf][0]), "r"(a[mf][1]), "r"(a[mf][2]), "r"(a[mf][3]),
                          "r"(b0), "r"(b1));
                }
            }
        }
        __syncthreads();
    }

    #pragma unroll
    for (int mf = 0; mf < 2; mf++) {
        int r0 = w * 32 + mf * 16 + (lane >> 2);
        #pragma unroll
        for (int j = 0; j < 8; j++) {
            int col = j * 8 + (lane & 3) * 2;
            float b0 = bias ? bias[col] : 0.f;
            float b1 = bias ? bias[col + 1] : 0.f;
            #pragma unroll
            for (int half2i = 0; half2i < 2; half2i++) {
                int vv = rowBase + r0 + half2i * 8;
                if (vv < NN) {
                    float c0 = acc[mf][j][half2i * 2 + 0] + b0;
                    float c1 = acc[mf][j][half2i * 2 + 1] + b1;
                    if (RELU) { c0 = fmaxf(c0, 0.f); c1 = fmaxf(c1, 0.f); }
                    if (HC) {
                        *(__half2*)((__half*)Cv + vv * ldc + col) = __floats2half2_rn(c0, c1);
                    } else {
                        float2 o = {c0, c1};
                        *(float2*)((float*)Cv + vv * ldc + col) = o;
                    }
                    if (C2v) {
                        if (HC2) {
                            *(__half2*)((__half*)C2v + vv * ldc2 + col) = __floats2half2_rn(c0, c1);
                        } else {
                            float2 o = {c0, c1};
                            *(float2*)((float*)C2v + vv * ldc2 + col) = o;
                        }
                    }
                }
            }
        }
    }
}

// ---------------- GCN projection: hn = (h2 @ Wg) * dinv ----------------
__global__ __launch_bounds__(256) void k_gcn_hn(const float* __restrict__ Wg) {
    __shared__ float w[64 * 16];
    int tid = threadIdx.x;
    for (int i = tid; i < 1024; i += 256) w[i] = Wg[i];
    __syncthreads();
    int v = blockIdx.x * 16 + (tid >> 4);
    int f = tid & 15;
    if (v >= NN) return;
    const float* h = g_h2 + v * 64;
    float acc = 0;
    #pragma unroll 8
    for (int j = 0; j < 64; j++) acc = fmaf(h[j], w[j * 16 + f], acc);
    float dinv = rsqrtf((float)(g_deg[v] + 1));
    g_hn[v * 16 + f] = acc * dinv;
}

// ---------------- fused GCN aggregation + head MLP ----------------
__global__ __launch_bounds__(256) void k_gcn_head(
    const float* __restrict__ x, const float* __restrict__ bg,
    const float* __restrict__ Wh1, const float* __restrict__ bh1,
    const float* __restrict__ Wh2, const float* __restrict__ bh2,
    float* __restrict__ out)
{
    __shared__ float w1[320], b1[10], w2[100], b2[10];
    __shared__ float sz[16][33];
    __shared__ float st[16][11];
    int tid = threadIdx.x;
    for (int i = tid; i < 320; i += 256) w1[i] = Wh1[i];
    for (int i = tid; i < 100; i += 256) w2[i] = Wh2[i];
    if (tid < 10) { b1[tid] = bh1[tid]; b2[tid] = bh2[tid]; }

    int n = tid >> 4, f = tid & 15;
    int v = blockIdx.x * 16 + n;
    if (v < NN) {
        int rs = g_rowptr[v], re = g_rowptr[v + 1];
        float s = g_hn[v * 16 + f];                 // self loop
        #pragma unroll 2
        for (int e = rs; e < re; e++)
            s += g_hn[g_bsrc[e] * 16 + f];
        float dinv = rsqrtf((float)(g_deg[v] + 1));
        sz[n][f]      = s * dinv + bg[f];
        sz[n][16 + f] = x[v * 16 + f];
    }
    __syncthreads();

    if (v < NN && f < 10) {
        float a = b1[f];
        #pragma unroll
        for (int i = 0; i < 32; i++) a = fmaf(sz[n][i], w1[i * 10 + f], a);
        st[n][f] = fmaxf(a, 0.f);
    }
    __syncthreads();

    if (v < NN && f < 10) {
        float a = b2[f];
        #pragma unroll
        for (int k = 0; k < 10; k++) a = fmaf(st[n][k], w2[k * 10 + f], a);
        out[v * 10 + f] = a;
    }
}

// ---------------- driver ----------------
extern "C" void kernel_launch(void* const* d_in, const int* in_sizes, int n_in,
                              void* d_out, int out_size) {
    const float* x     = (const float*)d_in[0];
    const int*   ei    = (const int*)  d_in[1];
    const float* ea    = (const float*)d_in[2];
    const float* We0   = (const float*)d_in[3];
    const float* be0   = (const float*)d_in[4];
    const float* Wpre0 = (const float*)d_in[5];
    const float* bpre0 = (const float*)d_in[6];
    const float* Wpost0= (const float*)d_in[7];
    const float* bpost0= (const float*)d_in[8];
    const float* Wlin0 = (const float*)d_in[9];
    const float* blin0 = (const float*)d_in[10];
    const float* We1   = (const float*)d_in[11];
    const float* be1   = (const float*)d_in[12];
    const float* Wpre1 = (const float*)d_in[13];
    const float* bpre1 = (const float*)d_in[14];
    const float* Wpost1= (const float*)d_in[15];
    const float* bpost1= (const float*)d_in[16];
    const float* Wlin1 = (const float*)d_in[17];
    const float* blin1 = (const float*)d_in[18];
    const float* Wg    = (const float*)d_in[19];
    const float* bg    = (const float*)d_in[20];
    const float* Wh1   = (const float*)d_in[21];
    const float* bh1   = (const float*)d_in[22];
    const float* Wh2   = (const float*)d_in[23];
    const float* bh2   = (const float*)d_in[24];
    float* out = (float*)d_out;

    const int* srcp = ei;
    const int* dstp = ei + NE;

    float  *p_cat0, *p_h1, *p_h2, *p_xd;
    __half *p_big_h, *p_xs_h;
    float  *p_Wcomb0, *p_bcomb0, *p_Wcomb1, *p_bcomb1, *p_xb1;
    int    *p_deg;
    cudaGetSymbolAddress((void**)&p_cat0,  g_cat0);
    cudaGetSymbolAddress((void**)&p_big_h, g_big_h);
    cudaGetSymbolAddress((void**)&p_h1,    g_h1);
    cudaGetSymbolAddress((void**)&p_h2,    g_h2);
    cudaGetSymbolAddress((void**)&p_xd,    g_xd);
    cudaGetSymbolAddress((void**)&p_xs_h,  g_xs_h);
    cudaGetSymbolAddress((void**)&p_Wcomb0,g_Wcomb0);
    cudaGetSymbolAddress((void**)&p_bcomb0,g_bcomb0);
    cudaGetSymbolAddress((void**)&p_Wcomb1,g_Wcomb1);
    cudaGetSymbolAddress((void**)&p_bcomb1,g_bcomb1);
    cudaGetSymbolAddress((void**)&p_xb1,   g_xb1);
    cudaGetSymbolAddress((void**)&p_deg,   g_deg);

    const int EB = (NE + 255) / 256;               // 6250
    const int SB = (NN + 1023) / 1024;             // 98
    const int TG = (NN + 127) / 128;               // 782
    const int XB = (NN * 32 + 255) / 256;          // 12500

    // CSR build
    cudaMemsetAsync(p_deg, 0, NN * sizeof(int));
    k_count<<<EB, 256>>>(dstp);
    k_scan1<<<SB, 1024>>>();
    k_scan23<<<SB, 1024>>>();
    k_scatter<<<EB, 256>>>(srcp, dstp, ea);

    // folds + xd0/xs0 (one kernel, independent segments)
    k_fold_xdxs<<<FOLD_BLOCKS + XB, 256>>>(We0, be0, Wpre0, bpre0,
                                           We1, be1, Wpre1, bpre1,
                                           Wpost0, bpost0, Wlin0, blin0,
                                           Wpost1, bpost1, Wlin1, blin1, x);

    // PNA layer 0
    k_agg0<<<(NN + 15) / 16, 256>>>();
    // h1 = relu(cat0 @ Wcomb0 + bcomb0); dual-store (half) into big[:, 0:64]
    k_gemm_tf32<3, true, false, false, true><<<TG, 128>>>(
        p_cat0, 96, p_Wcomb0, p_bcomb0, p_h1, 64, p_big_h, 384);

    // PNA layer 1
    k_gemm_tf32<2, false, false, false, false><<<TG, 128>>>(
        p_h1, 64, Wpre1, p_xb1, p_xd, 64, nullptr, 0);                        // xd1 (fp32)
    k_gemm_tf32<2, false, false, true, false><<<TG, 128>>>(
        p_h1, 64, Wpre1 + 64 * 64, nullptr, p_xs_h, 64, nullptr, 0);          // xs1 (fp16)
    k_agg1<<<(NN + 3) / 4, 256>>>();
    // h2 = relu(big_h @ Wcomb1 + bcomb1)  (half A)
    k_gemm_tf32<12, true, true, false, false><<<TG, 128>>>(
        p_big_h, 384, p_Wcomb1, p_bcomb1, p_h2, 64, nullptr, 0);

    // GCN + head
    k_gcn_hn<<<(NN + 15) / 16, 256>>>(Wg);
    k_gcn_head<<<(NN + 15) / 16, 256>>>(x, bg, Wh1, bh1, Wh2, bh2, out);
}

// round 17
// speedup vs baseline: 1.1211x; 1.1211x over previous
#include <cuda_runtime.h>
#include <cstdint>

#define NN 100000
#define NE 1600000

// ---------------- scratch (static __device__ — allocation-free) ----------------
__device__ int    g_deg[NN];
__device__ int    g_cursor[NN];
__device__ int    g_rowptr[NN + 1];
__device__ int    g_bsum[256];
__device__ int    g_bsrc[NE];
__device__ float4 g_battr[NE];
__device__ float  g_xd[NN * 64];
__device__ float  g_xs[NN * 64];
__device__ float  g_cat0[NN * 96];      // layer0 concat input [x | s mean mx mn std]
__device__ float  g_big[NN * 384];      // layer1 concat input
__device__ float  g_h1[NN * 64];
__device__ float  g_h2[NN * 64];
__device__ float  g_hn[NN * 16];
// folded weights
__device__ float  g_Wc0[4 * 16],  g_xb0[16];
__device__ float  g_Wc1[4 * 64],  g_xb1[64];
__device__ float  g_Wcomb0[96 * 64],  g_bcomb0[64];
__device__ float  g_Wcomb1[384 * 64], g_bcomb1[64];

// ---------------- CSR build ----------------
__global__ void k_count(const int* __restrict__ dst) {
    int e = blockIdx.x * blockDim.x + threadIdx.x;
    if (e < NE) atomicAdd(&g_deg[dst[e]], 1);
}

__global__ void k_scan1() {
    __shared__ int s[1024];
    int i = blockIdx.x * 1024 + threadIdx.x;
    int v = (i < NN) ? g_deg[i] : 0;
    s[threadIdx.x] = v;
    __syncthreads();
    for (int off = 1; off < 1024; off <<= 1) {
        int t = (threadIdx.x >= off) ? s[threadIdx.x - off] : 0;
        __syncthreads();
        s[threadIdx.x] += t;
        __syncthreads();
    }
    if (i < NN) g_rowptr[i] = s[threadIdx.x] - v;   // exclusive within block
    if (threadIdx.x == 1023) g_bsum[blockIdx.x] = s[1023];
}

// merged scan2+scan3: each block computes its own bsum prefix with one warp.
// Also initializes cursor = rowptr so scatter needs only ONE random access.
__global__ void k_scan23() {
    __shared__ int base;
    int b = blockIdx.x, tid = threadIdx.x;
    if (tid < 32) {
        int sum = 0;
        for (int i = tid; i < b; i += 32) sum += g_bsum[i];
        #pragma unroll
        for (int off = 16; off > 0; off >>= 1)
            sum += __shfl_xor_sync(0xffffffffu, sum, off);
        if (tid == 0) base = sum;
    }
    __syncthreads();
    int i = b * 1024 + tid;
    if (i < NN) {
        int rp = g_rowptr[i] + base;
        g_rowptr[i] = rp;
        g_cursor[i] = rp;
    }
    if (i == 0) g_rowptr[NN] = NE;
}

__global__ void k_scatter(const int* __restrict__ src, const int* __restrict__ dst,
                          const float* __restrict__ ea) {
    int e = blockIdx.x * blockDim.x + threadIdx.x;
    if (e >= NE) return;
    int d = dst[e];
    int p = atomicAdd(&g_cursor[d], 1);          // cursor pre-seeded with rowptr
    g_bsrc[p]  = src[e];
    g_battr[p] = ((const float4*)ea)[e];
}

// ---------------- fused weight folding + layer-0 xd/xs precompute ----------------
// blocks [0,121): folds (edge0 | edge1 | post0 | post1)
// blocks [121,...): xd0/xs0 + copy x into cat0 (self-contained bias fold)
#define FOLD_BLOCKS 121
__global__ void k_fold_xdxs(
    const float* __restrict__ We0,  const float* __restrict__ be0,
    const float* __restrict__ Wpre0,const float* __restrict__ bpre0,
    const float* __restrict__ We1,  const float* __restrict__ be1,
    const float* __restrict__ Wpre1,const float* __restrict__ bpre1,
    const float* __restrict__ Wpost0,const float* __restrict__ bpost0,
    const float* __restrict__ Wlin0, const float* __restrict__ blin0,
    const float* __restrict__ Wpost1,const float* __restrict__ bpost1,
    const float* __restrict__ Wlin1, const float* __restrict__ blin1,
    const float* __restrict__ x)
{
    if (blockIdx.x < FOLD_BLOCKS) {
        int idx = blockIdx.x * blockDim.x + threadIdx.x;
        if (idx < 16) {
            int f = idx;
            float a0 = 0, a1 = 0, a2 = 0, a3 = 0, b = bpre0[f];
            for (int j = 0; j < 16; j++) {
                float wv = Wpre0[(32 + j) * 16 + f];
                a0 = fmaf(We0[0 * 16 + j], wv, a0);
                a1 = fmaf(We0[1 * 16 + j], wv, a1);
                a2 = fmaf(We0[2 * 16 + j], wv, a2);
                a3 = fmaf(We0[3 * 16 + j], wv, a3);
                b  = fmaf(be0[j], wv, b);
            }
            g_Wc0[f] = a0; g_Wc0[16 + f] = a1; g_Wc0[32 + f] = a2; g_Wc0[48 + f] = a3;
            g_xb0[f] = b;
        } else if (idx < 80) {
            int f = idx - 16;
            float a0 = 0, a1 = 0, a2 = 0, a3 = 0, b = bpre1[f];
            for (int j = 0; j < 64; j++) {
                float wv = Wpre1[(128 + j) * 64 + f];
                a0 = fmaf(We1[0 * 64 + j], wv, a0);
                a1 = fmaf(We1[1 * 64 + j], wv, a1);
                a2 = fmaf(We1[2 * 64 + j], wv, a2);
                a3 = fmaf(We1[3 * 64 + j], wv, a3);
                b  = fmaf(be1[j], wv, b);
            }
            g_Wc1[f] = a0; g_Wc1[64 + f] = a1; g_Wc1[128 + f] = a2; g_Wc1[192 + f] = a3;
            g_xb1[f] = b;
        } else if (idx < 80 + 96 * 64 + 64) {
            int t = idx - 80;
            if (t < 96 * 64) {
                int k = t >> 6, f = t & 63;
                float a = 0;
                for (int j = 0; j < 64; j++) a = fmaf(Wpost0[k * 64 + j], Wlin0[j * 64 + f], a);
                g_Wcomb0[t] = a;
            } else {
                int f = t - 96 * 64;
                float a = blin0[f];
                for (int j = 0; j < 64; j++) a = fmaf(bpost0[j], Wlin0[j * 64 + f], a);
                g_bcomb0[f] = a;
            }
        } else if (idx < 80 + 96 * 64 + 64 + 384 * 64 + 64) {
            int t = idx - (80 + 96 * 64 + 64);
            if (t < 384 * 64) {
                int k = t >> 6, f = t & 63;
                float a = 0;
                for (int j = 0; j < 64; j++) a = fmaf(Wpost1[k * 64 + j], Wlin1[j * 64 + f], a);
                g_Wcomb1[t] = a;
            } else {
                int f = t - 384 * 64;
                float a = blin1[f];
                for (int j = 0; j < 64; j++) a = fmaf(bpost1[j], Wlin1[j * 64 + f], a);
                g_bcomb1[f] = a;
            }
        }
    } else {
        int t = (blockIdx.x - FOLD_BLOCKS) * blockDim.x + threadIdx.x;
        if (t >= NN * 32) return;
        int v = t >> 5, l = t & 31, f = l & 15;
        int rbase = (l < 16) ? 0 : 16;
        float acc = 0.f;
        if (l < 16) {                      // inline xb0 fold (independent of fold blocks)
            acc = bpre0[f];
            #pragma unroll
            for (int j = 0; j < 16; j++)
                acc = fmaf(be0[j], Wpre0[(32 + j) * 16 + f], acc);
        }
        const float* xr = x + v * 16;
        #pragma unroll
        for (int j = 0; j < 16; j++)
            acc = fmaf(xr[j], Wpre0[(rbase + j) * 16 + f], acc);
        if (l < 16) { g_xd[v * 16 + f] = acc; g_cat0[v * 96 + f] = xr[f]; }
        else        { g_xs[v * 16 + f] = acc; }
    }
}

// ---------------- PNA aggregation layer 0 (F=16, 16 lanes/node; serial loop) ----------------
__global__ __launch_bounds__(256) void k_agg0() {
    int tid = threadIdx.x;
    int v = blockIdx.x * 16 + (tid >> 4);
    int f = tid & 15;
    if (v >= NN) return;
    int rs = g_rowptr[v], re = g_rowptr[v + 1];
    float xdv = g_xd[v * 16 + f];
    float w0 = g_Wc0[f], w1 = g_Wc0[16 + f], w2 = g_Wc0[32 + f], w3 = g_Wc0[48 + f];
    float s = 0, sq = 0, mx = -3.402823e38f, mn = 3.402823e38f;
    #pragma unroll 2
    for (int e = rs; e < re; e++) {
        int sid = g_bsrc[e];
        float4 a = g_battr[e];
        float m = xdv + g_xs[sid * 16 + f];
        m = fmaf(a.x, w0, fmaf(a.y, w1, fmaf(a.z, w2, fmaf(a.w, w3, m))));
        s += m; sq = fmaf(m, m, sq); mx = fmaxf(mx, m); mn = fminf(mn, m);
    }
    int cnt = re - rs;
    float den = (float)(cnt > 0 ? cnt : 1);
    float mean = s / den, msq = sq / den;
    float sd = sqrtf(fmaxf(msq - mean * mean, 0.f) + 1e-5f);
    if (cnt == 0) { mx = 0.f; mn = 0.f; }
    float* o = g_cat0 + v * 96 + 16 + f;
    o[0] = s; o[16] = mean; o[32] = mx; o[48] = mn; o[64] = sd;
}

// ---------------- PNA aggregation layer 1 (F=64, 64 lanes/node; serial loop) ----------------
__global__ __launch_bounds__(256) void k_agg1() {
    int tid = threadIdx.x;
    int v = blockIdx.x * 4 + (tid >> 6);
    int f = tid & 63;
    if (v >= NN) return;
    int rs = g_rowptr[v], re = g_rowptr[v + 1];
    float xdv = g_xd[v * 64 + f];
    float w0 = g_Wc1[f], w1 = g_Wc1[64 + f], w2 = g_Wc1[128 + f], w3 = g_Wc1[192 + f];
    float s = 0, sq = 0, mx = -3.402823e38f, mn = 3.402823e38f;
    #pragma unroll 2
    for (int e = rs; e < re; e++) {
        int sid = g_bsrc[e];
        float4 a = g_battr[e];
        float m = xdv + g_xs[sid * 64 + f];
        m = fmaf(a.x, w0, fmaf(a.y, w1, fmaf(a.z, w2, fmaf(a.w, w3, m))));
        s += m; sq = fmaf(m, m, sq); mx = fmaxf(mx, m); mn = fminf(mn, m);
    }
    int cnt = re - rs;
    float den = (float)(cnt > 0 ? cnt : 1);
    float mean = s / den, msq = sq / den;
    float sd = sqrtf(fmaxf(msq - mean * mean, 0.f) + 1e-5f);
    if (cnt == 0) { mx = 0.f; mn = 0.f; }
    float* o = g_big + v * 384 + 64 + f;
    o[0] = s; o[64] = mean; o[128] = mx; o[192] = mn; o[256] = sd;
}

// ================ tf32 tensor-core GEMM: C[M,64] = A[M,KC*32] @ W + bias ================
#define TA 36
#define TB 72

__device__ __forceinline__ uint32_t f2tf32(float v) {
    uint32_t t;
    asm("cvt.rna.tf32.f32 %0, %1;" : "=r"(t) : "f"(v));
    return t;
}

template<int KC, bool RELU>
__global__ __launch_bounds__(128) void k_gemm_tf32(
    const float* __restrict__ A, int lda,
    const float* __restrict__ W,       // [KC*32, 64] fp32 (global)
    const float* __restrict__ bias,    // [64] or nullptr
    float* __restrict__ C, int ldc,
    float* __restrict__ C2, int ldc2)  // optional second store (nullptr to skip)
{
    __shared__ float sA[128 * TA];
    __shared__ float sB[32 * TB];
    int tid = threadIdx.x;
    int lane = tid & 31, w = tid >> 5;
    int rowBase = blockIdx.x * 128;

    float acc[2][8][4];
    #pragma unroll
    for (int mf = 0; mf < 2; mf++)
        #pragma unroll
        for (int j = 0; j < 8; j++)
            #pragma unroll
            for (int q = 0; q < 4; q++) acc[mf][j][q] = 0.f;

    for (int kc = 0; kc < KC; kc++) {
        #pragma unroll
        for (int i = 0; i < 32; i++) {
            int idx = tid + i * 128;
            int r = idx >> 5, k = idx & 31;
            int v = rowBase + r;
            float val = (v < NN) ? A[v * lda + kc * 32 + k] : 0.f;
            sA[r * TA + k] = __uint_as_float(f2tf32(val));
        }
        #pragma unroll
        for (int i = 0; i < 16; i++) {
            int idx = tid + i * 128;
            int k = idx >> 6, n = idx & 63;
            sB[k * TB + n] = __uint_as_float(f2tf32(W[(kc * 32 + k) * 64 + n]));
        }
        __syncthreads();
        #pragma unroll
        for (int ks = 0; ks < 4; ks++) {
            int kk = ks * 8;
            uint32_t a[2][4];
            #pragma unroll
            for (int mf = 0; mf < 2; mf++) {
                int r = w * 32 + mf * 16 + (lane >> 2);
                a[mf][0] = __float_as_uint(sA[r * TA + kk + (lane & 3)]);
                a[mf][1] = __float_as_uint(sA[(r + 8) * TA + kk + (lane & 3)]);
                a[mf][2] = __float_as_uint(sA[r * TA + kk + (lane & 3) + 4]);
                a[mf][3] = __float_as_uint(sA[(r + 8) * TA + kk + (lane & 3) + 4]);
            }
            #pragma unroll
            for (int j = 0; j < 8; j++) {
                uint32_t b0 = __float_as_uint(sB[(kk + (lane & 3)) * TB + j * 8 + (lane >> 2)]);
                uint32_t b1 = __float_as_uint(sB[(kk + (lane & 3) + 4) * TB + j * 8 + (lane >> 2)]);
                #pragma unroll
                for (int mf = 0; mf < 2; mf++) {
                    asm volatile(
                        "mma.sync.aligned.m16n8k8.row.col.f32.tf32.tf32.f32 "
                        "{%0,%1,%2,%3}, {%4,%5,%6,%7}, {%8,%9}, {%0,%1,%2,%3};"
                        : "+f"(acc[mf][j][0]), "+f"(acc[mf][j][1]),
                          "+f"(acc[mf][j][2]), "+f"(acc[mf][j][3])
                        : "r"(a[mf][0]), "r"(a[mf][1]), "r"(a[mf][2]), "r"(a[mf][3]),
                          "r"(b0), "r"(b1));
                }
            }
        }
        __syncthreads();
    }

    #pragma unroll
    for (int mf = 0; mf < 2; mf++) {
        int r0 = w * 32 + mf * 16 + (lane >> 2);
        #pragma unroll
        for (int j = 0; j < 8; j++) {
            int col = j * 8 + (lane & 3) * 2;
            float b0 = bias ? bias[col] : 0.f;
            float b1 = bias ? bias[col + 1] : 0.f;
            int v0 = rowBase + r0;
            if (v0 < NN) {
                float c0 = acc[mf][j][0] + b0, c1 = acc[mf][j][1] + b1;
                if (RELU) { c0 = fmaxf(c0, 0.f); c1 = fmaxf(c1, 0.f); }
                float2 o = {c0, c1};
                *(float2*)&C[v0 * ldc + col] = o;
                if (C2) *(float2*)&C2[v0 * ldc2 + col] = o;
            }
            int v1 = rowBase + r0 + 8;
            if (v1 < NN) {
                float c0 = acc[mf][j][2] + b0, c1 = acc[mf][j][3] + b1;
                if (RELU) { c0 = fmaxf(c0, 0.f); c1 = fmaxf(c1, 0.f); }
                float2 o = {c0, c1};
                *(float2*)&C[v1 * ldc + col] = o;
                if (C2) *(float2*)&C2[v1 * ldc2 + col] = o;
            }
        }
    }
}

// ---------------- GCN projection: hn = (h2 @ Wg) * dinv ----------------
__global__ __launch_bounds__(256) void k_gcn_hn(const float* __restrict__ Wg) {
    __shared__ float w[64 * 16];
    int tid = threadIdx.x;
    for (int i = tid; i < 1024; i += 256) w[i] = Wg[i];
    __syncthreads();
    int v = blockIdx.x * 16 + (tid >> 4);
    int f = tid & 15;
    if (v >= NN) return;
    const float* h = g_h2 + v * 64;
    float acc = 0;
    #pragma unroll 8
    for (int j = 0; j < 64; j++) acc = fmaf(h[j], w[j * 16 + f], acc);
    float dinv = rsqrtf((float)(g_deg[v] + 1));
    g_hn[v * 16 + f] = acc * dinv;
}

// ---------------- fused GCN aggregation + head MLP ----------------
__global__ __launch_bounds__(256) void k_gcn_head(
    const float* __restrict__ x, const float* __restrict__ bg,
    const float* __restrict__ Wh1, const float* __restrict__ bh1,
    const float* __restrict__ Wh2, const float* __restrict__ bh2,
    float* __restrict__ out)
{
    __shared__ float w1[320], b1[10], w2[100], b2[10];
    __shared__ float sz[16][33];
    __shared__ float st[16][11];
    int tid = threadIdx.x;
    for (int i = tid; i < 320; i += 256) w1[i] = Wh1[i];
    for (int i = tid; i < 100; i += 256) w2[i] = Wh2[i];
    if (tid < 10) { b1[tid] = bh1[tid]; b2[tid] = bh2[tid]; }

    int n = tid >> 4, f = tid & 15;
    int v = blockIdx.x * 16 + n;
    if (v < NN) {
        int rs = g_rowptr[v], re = g_rowptr[v + 1];
        float s = g_hn[v * 16 + f];                 // self loop
        #pragma unroll 2
        for (int e = rs; e < re; e++)
            s += g_hn[g_bsrc[e] * 16 + f];
        float dinv = rsqrtf((float)(g_deg[v] + 1));
        sz[n][f]      = s * dinv + bg[f];
        sz[n][16 + f] = x[v * 16 + f];
    }
    __syncthreads();

    if (v < NN && f < 10) {
        float a = b1[f];
        #pragma unroll
        for (int i = 0; i < 32; i++) a = fmaf(sz[n][i], w1[i * 10 + f], a);
        st[n][f] = fmaxf(a, 0.f);
    }
    __syncthreads();

    if (v < NN && f < 10) {
        float a = b2[f];
        #pragma unroll
        for (int k = 0; k < 10; k++) a = fmaf(st[n][k], w2[k * 10 + f], a);
        out[v * 10 + f] = a;
    }
}

// ---------------- driver ----------------
extern "C" void kernel_launch(void* const* d_in, const int* in_sizes, int n_in,
                              void* d_out, int out_size) {
    const float* x     = (const float*)d_in[0];
    const int*   ei    = (const int*)  d_in[1];
    const float* ea    = (const float*)d_in[2];
    const float* We0   = (const float*)d_in[3];
    const float* be0   = (const float*)d_in[4];
    const float* Wpre0 = (const float*)d_in[5];
    const float* bpre0 = (const float*)d_in[6];
    const float* Wpost0= (const float*)d_in[7];
    const float* bpost0= (const float*)d_in[8];
    const float* Wlin0 = (const float*)d_in[9];
    const float* blin0 = (const float*)d_in[10];
    const float* We1   = (const float*)d_in[11];
    const float* be1   = (const float*)d_in[12];
    const float* Wpre1 = (const float*)d_in[13];
    const float* bpre1 = (const float*)d_in[14];
    const float* Wpost1= (const float*)d_in[15];
    const float* bpost1= (const float*)d_in[16];
    const float* Wlin1 = (const float*)d_in[17];
    const float* blin1 = (const float*)d_in[18];
    const float* Wg    = (const float*)d_in[19];
    const float* bg    = (const float*)d_in[20];
    const float* Wh1   = (const float*)d_in[21];
    const float* bh1   = (const float*)d_in[22];
    const float* Wh2   = (const float*)d_in[23];
    const float* bh2   = (const float*)d_in[24];
    float* out = (float*)d_out;

    const int* srcp = ei;
    const int* dstp = ei + NE;

    float *p_cat0, *p_big, *p_h1, *p_h2, *p_xd, *p_xs;
    float *p_Wcomb0, *p_bcomb0, *p_Wcomb1, *p_bcomb1, *p_xb1;
    int   *p_deg;
    cudaGetSymbolAddress((void**)&p_cat0,  g_cat0);
    cudaGetSymbolAddress((void**)&p_big,   g_big);
    cudaGetSymbolAddress((void**)&p_h1,    g_h1);
    cudaGetSymbolAddress((void**)&p_h2,    g_h2);
    cudaGetSymbolAddress((void**)&p_xd,    g_xd);
    cudaGetSymbolAddress((void**)&p_xs,    g_xs);
    cudaGetSymbolAddress((void**)&p_Wcomb0,g_Wcomb0);
    cudaGetSymbolAddress((void**)&p_bcomb0,g_bcomb0);
    cudaGetSymbolAddress((void**)&p_Wcomb1,g_Wcomb1);
    cudaGetSymbolAddress((void**)&p_bcomb1,g_bcomb1);
    cudaGetSymbolAddress((void**)&p_xb1,   g_xb1);
    cudaGetSymbolAddress((void**)&p_deg,   g_deg);

    const int EB = (NE + 255) / 256;               // 6250
    const int SB = (NN + 1023) / 1024;             // 98
    const int TG = (NN + 127) / 128;               // 782
    const int XB = (NN * 32 + 255) / 256;          // 12500

    // CSR build
    cudaMemsetAsync(p_deg, 0, NN * sizeof(int));
    k_count<<<EB, 256>>>(dstp);
    k_scan1<<<SB, 1024>>>();
    k_scan23<<<SB, 1024>>>();
    k_scatter<<<EB, 256>>>(srcp, dstp, ea);

    // folds + xd0/xs0 (one kernel, independent segments)
    k_fold_xdxs<<<FOLD_BLOCKS + XB, 256>>>(We0, be0, Wpre0, bpre0,
                                           We1, be1, Wpre1, bpre1,
                                           Wpost0, bpost0, Wlin0, blin0,
                                           Wpost1, bpost1, Wlin1, blin1, x);

    // PNA layer 0
    k_agg0<<<(NN + 15) / 16, 256>>>();
    // h1 = relu(cat0 @ Wcomb0 + bcomb0); dual-store into big[:, 0:64]
    k_gemm_tf32<3, true><<<TG, 128>>>(p_cat0, 96, p_Wcomb0, p_bcomb0,
                                      p_h1, 64, p_big, 384);

    // PNA layer 1
    k_gemm_tf32<2, false><<<TG, 128>>>(p_h1, 64, Wpre1, p_xb1,
                                       p_xd, 64, (float*)nullptr, 0);            // xd1
    k_gemm_tf32<2, false><<<TG, 128>>>(p_h1, 64, Wpre1 + 64 * 64, (float*)nullptr,
                                       p_xs, 64, (float*)nullptr, 0);            // xs1
    k_agg1<<<(NN + 3) / 4, 256>>>();
    // h2 = relu(big @ Wcomb1 + bcomb1)
    k_gemm_tf32<12, true><<<TG, 128>>>(p_big, 384, p_Wcomb1, p_bcomb1,
                                       p_h2, 64, (float*)nullptr, 0);

    // GCN + head
    k_gcn_hn<<<(NN + 15) / 16, 256>>>(Wg);
    k_gcn_head<<<(NN + 15) / 16, 256>>>(x, bg, Wh1, bh1, Wh2, bh2, out);
}